// round 4
// baseline (speedup 1.0000x reference)
#include <cuda_runtime.h>

// Erosion2d: 3x3 windowed min, stride 1, pad value 1e9, over (16,64,256,256) fp32.
// Separable horizontal 3-min + register-rolled vertical 3-min.
// R4 changes vs R3 (86.0us, DRAM 78.8%):
//   - T 8 -> 16: read amplification (T+2)/T 1.25x -> 1.125x
//   - __stcs streaming stores: don't let output evict input halo lines from L2

#define PAD_VALF 1e9f

constexpr int H = 256;
constexpr int W = 256;
constexpr int W4 = W / 4;   // 64 float4 lanes per row
constexpr int T  = 16;      // rows per thread (read amplification 1.125x)

__device__ __forceinline__ float4 fmin4(float4 a, float4 b) {
    float4 r;
    r.x = fminf(a.x, b.x);
    r.y = fminf(a.y, b.y);
    r.z = fminf(a.z, b.z);
    r.w = fminf(a.w, b.w);
    return r;
}

__global__ __launch_bounds__(256) void erosion3x3_kernel(
    const float* __restrict__ in, float* __restrict__ out)
{
    const int x4 = threadIdx.x;                                   // 0..63
    const int xb = x4 * 4;
    const int y0 = (blockIdx.y * blockDim.y + threadIdx.y) * T;   // strip top
    const long long plane = blockIdx.z;                           // n*c plane

    const float* __restrict__ p = in  + plane * (long long)(H * W);
    float*       __restrict__ q = out + plane * (long long)(H * W);

    const bool left_edge  = (x4 == 0);
    const bool right_edge = (x4 == W4 - 1);

    // Horizontal 3-min of row y for this thread's 4 output columns.
    auto hmin_row = [&](int y) -> float4 {
        const float* row = p + y * W + xb;
        float4 v = *reinterpret_cast<const float4*>(row);
        float l = left_edge  ? PAD_VALF : __ldg(row - 1);
        float r = right_edge ? PAD_VALF : __ldg(row + 4);
        float4 h;
        h.x = fminf(l,   fminf(v.x, v.y));
        h.y = fminf(v.x, fminf(v.y, v.z));
        h.z = fminf(v.y, fminf(v.z, v.w));
        h.w = fminf(v.z, fminf(v.w, r));
        return h;
    };

    const float4 padv = make_float4(PAD_VALF, PAD_VALF, PAD_VALF, PAD_VALF);

    // Rolling 3-row window of horizontal mins: a = y-1, b = y, c = y+1.
    float4 a = (y0 > 0) ? hmin_row(y0 - 1) : padv;
    float4 b = hmin_row(y0);

    #pragma unroll
    for (int i = 0; i < T; i++) {
        const int y = y0 + i;
        float4 c = (y + 1 < H) ? hmin_row(y + 1) : padv;
        float4 o = fmin4(a, fmin4(b, c));
        // Streaming store: evict-first in L2 so output doesn't displace the
        // input lines that strip-boundary halo re-reads depend on.
        __stcs(reinterpret_cast<float4*>(q + y * W + xb), o);
        a = b;
        b = c;
    }
}

extern "C" void kernel_launch(void* const* d_in, const int* in_sizes, int n_in,
                              void* d_out, int out_size)
{
    const float* x = (const float*)d_in[0];
    float* out = (float*)d_out;

    const int planes = in_sizes[0] / (H * W);   // 16 * 64 = 1024

    dim3 block(W4, 4, 1);                 // 64 x 4 = 256 threads
    dim3 grid(1, H / (4 * T), planes);    // (1, 4, 1024)
    erosion3x3_kernel<<<grid, block>>>(x, out);
}

// round 6
// speedup vs baseline: 1.0652x; 1.0652x over previous
#include <cuda_runtime.h>

// Erosion2d: 3x3 windowed min, stride 1, pad value 1e9, over (16,64,256,256) fp32.
// R5 (resubmit; prior round was a broker timeout, kernel never ran):
// R3 config (T=8, plain stores, grid 8192 — best: 86.0us, DRAM 78.8%) with one
// change: intra-warp horizontal halos via warp shuffle instead of scalar __ldg
// (removes ~2/3 of LDG instructions -> less L1tex queue pressure).
// R4 (T=16 + __stcs) regressed to 92us: fewer waves + evict-first stores hurt.

#define PAD_VALF 1e9f

constexpr int H = 256;
constexpr int W = 256;
constexpr int W4 = W / 4;   // 64 float4 lanes per row
constexpr int T  = 8;       // rows per thread

__device__ __forceinline__ float4 fmin4(float4 a, float4 b) {
    float4 r;
    r.x = fminf(a.x, b.x);
    r.y = fminf(a.y, b.y);
    r.z = fminf(a.z, b.z);
    r.w = fminf(a.w, b.w);
    return r;
}

__global__ __launch_bounds__(256) void erosion3x3_kernel(
    const float* __restrict__ in, float* __restrict__ out)
{
    const int x4   = threadIdx.x;                                 // 0..63
    const int xb   = x4 * 4;
    const int lane = threadIdx.x & 31;                            // warp spans 32 consecutive x4, same y
    const int y0 = (blockIdx.y * blockDim.y + threadIdx.y) * T;   // strip top
    const long long plane = blockIdx.z;                           // n*c plane

    const float* __restrict__ p = in  + plane * (long long)(H * W);
    float*       __restrict__ q = out + plane * (long long)(H * W);

    const bool left_edge  = (x4 == 0);
    const bool right_edge = (x4 == W4 - 1);

    // Horizontal 3-min of row y for this thread's 4 output columns.
    // Cross-lane neighbors come from warp shuffles; only warp-edge lanes
    // touch memory for the halo.
    auto hmin_row = [&](int y) -> float4 {
        const float* row = p + y * W + xb;
        float4 v = *reinterpret_cast<const float4*>(row);
        float lw = __shfl_up_sync(0xffffffffu, v.w, 1);   // lane i-1's v.w
        float rx = __shfl_down_sync(0xffffffffu, v.x, 1); // lane i+1's v.x
        float l, r;
        if (lane == 0)  l = left_edge  ? PAD_VALF : __ldg(row - 1);
        else            l = lw;
        if (lane == 31) r = right_edge ? PAD_VALF : __ldg(row + 4);
        else            r = rx;
        float4 h;
        h.x = fminf(l,   fminf(v.x, v.y));
        h.y = fminf(v.x, fminf(v.y, v.z));
        h.z = fminf(v.y, fminf(v.z, v.w));
        h.w = fminf(v.z, fminf(v.w, r));
        return h;
    };

    const float4 padv = make_float4(PAD_VALF, PAD_VALF, PAD_VALF, PAD_VALF);

    // Rolling 3-row window of horizontal mins: a = y-1, b = y, c = y+1.
    float4 a = (y0 > 0) ? hmin_row(y0 - 1) : padv;
    float4 b = hmin_row(y0);

    #pragma unroll
    for (int i = 0; i < T; i++) {
        const int y = y0 + i;
        float4 c = (y + 1 < H) ? hmin_row(y + 1) : padv;
        float4 o = fmin4(a, fmin4(b, c));
        *reinterpret_cast<float4*>(q + y * W + xb) = o;
        a = b;
        b = c;
    }
}

extern "C" void kernel_launch(void* const* d_in, const int* in_sizes, int n_in,
                              void* d_out, int out_size)
{
    const float* x = (const float*)d_in[0];
    float* out = (float*)d_out;

    const int planes = in_sizes[0] / (H * W);   // 16 * 64 = 1024

    dim3 block(W4, 4, 1);                 // 64 x 4 = 256 threads
    dim3 grid(1, H / (4 * T), planes);    // (1, 8, 1024)
    erosion3x3_kernel<<<grid, block>>>(x, out);
}

// round 7
// speedup vs baseline: 1.0699x; 1.0045x over previous
#include <cuda_runtime.h>

// Erosion2d: 3x3 windowed min, stride 1, pad value 1e9, over (16,64,256,256) fp32.
// FINAL (R3 config, re-bench for stability): separable horizontal 3-min +
// register-rolled vertical 3-min, float4 I/O, T=8 rows/thread, grid 8192 CTAs.
//
// Measured history:
//   R3 (this): 86.0us, DRAM 78.8%, 6243 GB/s  <- best
//   R4 T=16 + __stcs:  92.0us (fewer waves + evict-first stores regressed)
//   R5 shuffle halos:  86.4us (L1% 48.6->39.0 but dur neutral -> L1 not binding)
// DRAM traffic is at the compulsory floor; 6.24 TB/s ~ mixed-stream HBM ceiling.

#define PAD_VALF 1e9f

constexpr int H = 256;
constexpr int W = 256;
constexpr int W4 = W / 4;   // 64 float4 lanes per row
constexpr int T  = 8;       // rows per thread

__device__ __forceinline__ float4 fmin4(float4 a, float4 b) {
    float4 r;
    r.x = fminf(a.x, b.x);
    r.y = fminf(a.y, b.y);
    r.z = fminf(a.z, b.z);
    r.w = fminf(a.w, b.w);
    return r;
}

__global__ __launch_bounds__(256) void erosion3x3_kernel(
    const float* __restrict__ in, float* __restrict__ out)
{
    const int x4 = threadIdx.x;                                   // 0..63
    const int xb = x4 * 4;
    const int y0 = (blockIdx.y * blockDim.y + threadIdx.y) * T;   // strip top
    const long long plane = blockIdx.z;                           // n*c plane

    const float* __restrict__ p = in  + plane * (long long)(H * W);
    float*       __restrict__ q = out + plane * (long long)(H * W);

    const bool left_edge  = (x4 == 0);
    const bool right_edge = (x4 == W4 - 1);

    // Horizontal 3-min of row y for this thread's 4 output columns.
    auto hmin_row = [&](int y) -> float4 {
        const float* row = p + y * W + xb;
        float4 v = *reinterpret_cast<const float4*>(row);
        float l = left_edge  ? PAD_VALF : __ldg(row - 1);
        float r = right_edge ? PAD_VALF : __ldg(row + 4);
        float4 h;
        h.x = fminf(l,   fminf(v.x, v.y));
        h.y = fminf(v.x, fminf(v.y, v.z));
        h.z = fminf(v.y, fminf(v.z, v.w));
        h.w = fminf(v.z, fminf(v.w, r));
        return h;
    };

    const float4 padv = make_float4(PAD_VALF, PAD_VALF, PAD_VALF, PAD_VALF);

    // Rolling 3-row window of horizontal mins: a = y-1, b = y, c = y+1.
    float4 a = (y0 > 0) ? hmin_row(y0 - 1) : padv;
    float4 b = hmin_row(y0);

    #pragma unroll
    for (int i = 0; i < T; i++) {
        const int y = y0 + i;
        float4 c = (y + 1 < H) ? hmin_row(y + 1) : padv;
        float4 o = fmin4(a, fmin4(b, c));
        *reinterpret_cast<float4*>(q + y * W + xb) = o;
        a = b;
        b = c;
    }
}

extern "C" void kernel_launch(void* const* d_in, const int* in_sizes, int n_in,
                              void* d_out, int out_size)
{
    const float* x = (const float*)d_in[0];
    float* out = (float*)d_out;

    const int planes = in_sizes[0] / (H * W);   // 16 * 64 = 1024

    dim3 block(W4, 4, 1);                 // 64 x 4 = 256 threads
    dim3 grid(1, H / (4 * T), planes);    // (1, 8, 1024)
    erosion3x3_kernel<<<grid, block>>>(x, out);
}

// round 14
// speedup vs baseline: 1.0894x; 1.0182x over previous
#include <cuda_runtime.h>

// Erosion2d: 3x3 windowed min, stride 1, pad value 1e9, over (16,64,256,256) fp32.
// R8 resubmit x6 (six consecutive broker timeouts; this variant has never run).
// T sweep completion. History:
//   T=16 (4096 CTAs): 92.0us  |  T=8 (8192 CTAs): 86.0us (stable, 2 runs)
// Trend favors more/smaller CTAs -> try T=4 (16384 CTAs, ~14 waves).
// Nominal read amplification 1.5x, but halo rows are L2-absorbed (adjacent
// y-strips are adjacent blockIdx.y -> temporally close -> L2 hits), so DRAM
// traffic should stay at the ~537MB compulsory floor.

#define PAD_VALF 1e9f

constexpr int H = 256;
constexpr int W = 256;
constexpr int W4 = W / 4;   // 64 float4 lanes per row
constexpr int T  = 4;       // rows per thread

__device__ __forceinline__ float4 fmin4(float4 a, float4 b) {
    float4 r;
    r.x = fminf(a.x, b.x);
    r.y = fminf(a.y, b.y);
    r.z = fminf(a.z, b.z);
    r.w = fminf(a.w, b.w);
    return r;
}

__global__ __launch_bounds__(256) void erosion3x3_kernel(
    const float* __restrict__ in, float* __restrict__ out)
{
    const int x4 = threadIdx.x;                                   // 0..63
    const int xb = x4 * 4;
    const int y0 = (blockIdx.y * blockDim.y + threadIdx.y) * T;   // strip top
    const long long plane = blockIdx.z;                           // n*c plane

    const float* __restrict__ p = in  + plane * (long long)(H * W);
    float*       __restrict__ q = out + plane * (long long)(H * W);

    const bool left_edge  = (x4 == 0);
    const bool right_edge = (x4 == W4 - 1);

    // Horizontal 3-min of row y for this thread's 4 output columns.
    auto hmin_row = [&](int y) -> float4 {
        const float* row = p + y * W + xb;
        float4 v = *reinterpret_cast<const float4*>(row);
        float l = left_edge  ? PAD_VALF : __ldg(row - 1);
        float r = right_edge ? PAD_VALF : __ldg(row + 4);
        float4 h;
        h.x = fminf(l,   fminf(v.x, v.y));
        h.y = fminf(v.x, fminf(v.y, v.z));
        h.z = fminf(v.y, fminf(v.z, v.w));
        h.w = fminf(v.z, fminf(v.w, r));
        return h;
    };

    const float4 padv = make_float4(PAD_VALF, PAD_VALF, PAD_VALF, PAD_VALF);

    // Rolling 3-row window of horizontal mins: a = y-1, b = y, c = y+1.
    float4 a = (y0 > 0) ? hmin_row(y0 - 1) : padv;
    float4 b = hmin_row(y0);

    #pragma unroll
    for (int i = 0; i < T; i++) {
        const int y = y0 + i;
        float4 c = (y + 1 < H) ? hmin_row(y + 1) : padv;
        float4 o = fmin4(a, fmin4(b, c));
        *reinterpret_cast<float4*>(q + y * W + xb) = o;
        a = b;
        b = c;
    }
}

extern "C" void kernel_launch(void* const* d_in, const int* in_sizes, int n_in,
                              void* d_out, int out_size)
{
    const float* x = (const float*)d_in[0];
    float* out = (float*)d_out;

    const int planes = in_sizes[0] / (H * W);   // 16 * 64 = 1024

    dim3 block(W4, 4, 1);                 // 64 x 4 = 256 threads
    dim3 grid(1, H / (4 * T), planes);    // (1, 16, 1024)
    erosion3x3_kernel<<<grid, block>>>(x, out);
}